// round 15
// baseline (speedup 1.0000x reference)
#include <cuda_runtime.h>
#include <cuda_fp16.h>
#include <math_constants.h>
#include <cstdint>

#define D_MODEL 1024
#define N_HEADS 16
#define HEAD_DIM 64
#define SEQ 1024
#define BATCH 32
#define M_TOK (BATCH * SEQ)   // 32768 tokens
#define SLOT_SZ ((size_t)M_TOK * D_MODEL)

// ---------------------------------------------------------------------------
// Scratch (alloc-free rule: __device__ globals).
// ---------------------------------------------------------------------------
__device__ __half g_xhi[SLOT_SZ];
__device__ __half g_xlo[SLOT_SZ];
__device__ __half g_wthi[(size_t)4 * D_MODEL * D_MODEL];
__device__ __half g_wtlo[(size_t)4 * D_MODEL * D_MODEL];
__device__ __half g_qkvh[3 * SLOT_SZ];
__device__ __half g_qkvl[3 * SLOT_SZ];
__device__ __half g_ch[SLOT_SZ];

// ---------------------------------------------------------------------------
// PTX helpers — plain compute_103-legal only (mma.sync / ldmatrix / cp.async).
// ---------------------------------------------------------------------------
__device__ __forceinline__ uint32_t smem_to_u32(const void* p) {
    uint32_t a;
    asm("{ .reg .u64 t; cvta.to.shared.u64 t, %1; cvt.u32.u64 %0, t; }" : "=r"(a) : "l"(p));
    return a;
}

#define CP_ASYNC16(sa, gp) \
    asm volatile("cp.async.cg.shared.global [%0], [%1], 16;" :: "r"(sa), "l"(gp))
#define CP_COMMIT() asm volatile("cp.async.commit_group;" ::: "memory")
#define CP_WAIT0()  asm volatile("cp.async.wait_group 0;" ::: "memory")

#define LDSM_X4(r, a) \
    asm volatile("ldmatrix.sync.aligned.m8n8.x4.shared.b16 {%0,%1,%2,%3}, [%4];" \
        : "=r"((r)[0]), "=r"((r)[1]), "=r"((r)[2]), "=r"((r)[3]) : "r"(a))

#define LDSM_X4_T(r, a) \
    asm volatile("ldmatrix.sync.aligned.m8n8.x4.trans.shared.b16 {%0,%1,%2,%3}, [%4];" \
        : "=r"((r)[0]), "=r"((r)[1]), "=r"((r)[2]), "=r"((r)[3]) : "r"(a))

#define MMA16816(c, a, b0v, b1v) \
    asm volatile("mma.sync.aligned.m16n8k16.row.col.f32.f16.f16.f32 " \
        "{%0,%1,%2,%3}, {%4,%5,%6,%7}, {%8,%9}, {%0,%1,%2,%3};" \
        : "+f"((c)[0]), "+f"((c)[1]), "+f"((c)[2]), "+f"((c)[3]) \
        : "r"((a)[0]), "r"((a)[1]), "r"((a)[2]), "r"((a)[3]), "r"(b0v), "r"(b1v))

__device__ __forceinline__ uint32_t pack_f16_hi(float a, float b) {
    __half2 t;
    t.x = __float2half_rn(a);
    t.y = __float2half_rn(b);
    return *(uint32_t*)&t;
}
__device__ __forceinline__ uint32_t pack_f16_lo(float a, float b) {
    __half ha = __float2half_rn(a), hb = __float2half_rn(b);
    __half2 t;
    t.x = __float2half_rn(a - __half2float(ha));
    t.y = __float2half_rn(b - __half2float(hb));
    return *(uint32_t*)&t;
}

// ---------------------------------------------------------------------------
// GEMM: C[M,N] = A[M,K] * B[N,K]^T, fp16 hi/lo via mma.sync.
// Block 128x128, 8 warps (2x4), warp tile 64x32, 256 threads,
// TWO CTAs per SM (launch_bounds(256,2): regs<=128) -> 4 warps/SMSP.
// K-chunk 32, 2-stage cp.async pipeline.
// NT=3: Ah*Bh+Al*Bh+Ah*Bl.  NT=1: Ah*Bh.
// bfmode=0: fp32 out. bfmode=1: fp16 hi(/lo) split out, slot-structured.
// ---------------------------------------------------------------------------
#define PADB 80                           // 64B of K data + 16B pad
#define STG_AL 10240                      // 128*80
#define STG_BH 20480
#define STG_BL 30720
#define STAGE_BYTES 40960
#define GEMM_SMEM (2 * STAGE_BYTES)       // 81920 B/CTA -> 163840 for 2 CTAs

template <int NT>
__global__ __launch_bounds__(256, 2)
void gemm_mma_f16(const __half* __restrict__ Ahi, const __half* __restrict__ Alo,
                  const __half* __restrict__ Bhi, const __half* __restrict__ Blo,
                  float* __restrict__ Cf,
                  __half* __restrict__ Ohi, __half* __restrict__ Olo,
                  float scale, int bfmode, int slot_base, int M, int N, int K)
{
    extern __shared__ char smc[];
    const uint32_t sbase = smem_to_u32(smc);
    const int tid = threadIdx.x;
    const int lane = tid & 31, wid = tid >> 5;       // 0..7
    const int wm = wid >> 2, wn = wid & 3;           // warp grid 2(M) x 4(N)
    const int m0 = blockIdx.y * 128, n0 = blockIdx.x * 128;

    float acc[4][4][4];
#pragma unroll
    for (int i = 0; i < 4; i++)
#pragma unroll
        for (int j = 0; j < 4; j++)
#pragma unroll
            for (int r = 0; r < 4; r++) acc[i][j][r] = 0.f;

    const uint32_t aoff = (uint32_t)((wm * 64 + (lane & 15)) * PADB + ((lane >> 4) & 1) * 16);
    const uint32_t boff = (uint32_t)((wn * 32 + (lane & 7) + ((lane >> 4) & 1) * 8) * PADB
                                     + ((lane >> 3) & 1) * 16);

    auto load_stage = [&](int ch, int st) {
        const uint32_t sb = sbase + st * STAGE_BYTES;
        const size_t k0b = (size_t)ch * 64;           // 32 halves = 64 bytes
#pragma unroll
        for (int i = 0; i < 2; i++) {    // 128 rows x 4 x 16B per operand
            int s = tid + 256 * i;       // 0..511
            int row = s >> 2, c = s & 3;
            uint32_t so = (uint32_t)(row * PADB + c * 16);
            size_t ga = (size_t)(m0 + row) * K * 2 + k0b + c * 16;
            size_t gb = (size_t)(n0 + row) * K * 2 + k0b + c * 16;
            CP_ASYNC16(sb + so,          (const char*)Ahi + ga);
            CP_ASYNC16(sb + STG_BH + so, (const char*)Bhi + gb);
            if (NT >= 2) CP_ASYNC16(sb + STG_AL + so, (const char*)Alo + ga);
            if (NT == 3) CP_ASYNC16(sb + STG_BL + so, (const char*)Blo + gb);
        }
        CP_COMMIT();
    };

    const int NC = K / 32;               // 32 chunks
    load_stage(0, 0);

#pragma unroll 1
    for (int ch = 0; ch < NC; ch++) {
        const int st = ch & 1;
        CP_WAIT0();
        __syncthreads();                 // orders compute(ch-1) on stage st^1
        if (ch + 1 < NC) load_stage(ch + 1, st ^ 1);

        const uint32_t sb = sbase + st * STAGE_BYTES;
#pragma unroll
        for (int ks = 0; ks < 2; ks++) {
            const uint32_t kb = ks * 32;
            uint32_t ah[4][4], al[4][4];
#pragma unroll
            for (int i = 0; i < 4; i++) {
                LDSM_X4(ah[i], sb + aoff + i * (16 * PADB) + kb);
                if (NT >= 2) LDSM_X4(al[i], sb + STG_AL + aoff + i * (16 * PADB) + kb);
            }
#pragma unroll
            for (int j = 0; j < 2; j++) {   // 2 x n16
                uint32_t bh4[4], bl4[4];
                LDSM_X4(bh4, sb + STG_BH + boff + j * (16 * PADB) + kb);
                if (NT == 3) LDSM_X4(bl4, sb + STG_BL + boff + j * (16 * PADB) + kb);
#pragma unroll
                for (int i = 0; i < 4; i++)
#pragma unroll
                    for (int hf = 0; hf < 2; hf++)
                        MMA16816(acc[i][j * 2 + hf], ah[i], bh4[hf * 2], bh4[hf * 2 + 1]);
                if (NT >= 2) {
#pragma unroll
                    for (int i = 0; i < 4; i++)
#pragma unroll
                        for (int hf = 0; hf < 2; hf++)
                            MMA16816(acc[i][j * 2 + hf], al[i], bh4[hf * 2], bh4[hf * 2 + 1]);
                }
                if (NT == 3) {
#pragma unroll
                    for (int i = 0; i < 4; i++)
#pragma unroll
                        for (int hf = 0; hf < 2; hf++)
                            MMA16816(acc[i][j * 2 + hf], ah[i], bl4[hf * 2], bl4[hf * 2 + 1]);
                }
            }
        }
    }

    const int r = lane >> 2, cl = (lane & 3) * 2;
    if (!bfmode) {
#pragma unroll
        for (int i = 0; i < 4; i++)
#pragma unroll
            for (int j8 = 0; j8 < 4; j8++) {
                int row = m0 + wm * 64 + i * 16 + r;
                int col = n0 + wn * 32 + j8 * 8 + cl;
                *(float2*)(Cf + (size_t)row * N + col) =
                    make_float2(acc[i][j8][0], acc[i][j8][1]);
                *(float2*)(Cf + (size_t)(row + 8) * N + col) =
                    make_float2(acc[i][j8][2], acc[i][j8][3]);
            }
    } else {
#pragma unroll
        for (int i = 0; i < 4; i++)
#pragma unroll
            for (int j8 = 0; j8 < 4; j8++) {
                int row = m0 + wm * 64 + i * 16 + r;
                int col = n0 + wn * 32 + j8 * 8 + cl;
                int slot = slot_base + (col >> 10), cw = col & 1023;
                float sc = (slot == 0) ? scale : 1.0f;
                size_t base = (size_t)slot * SLOT_SZ;
                float v0 = acc[i][j8][0] * sc, v1 = acc[i][j8][1] * sc;
                float v2 = acc[i][j8][2] * sc, v3 = acc[i][j8][3] * sc;
                size_t i0 = base + (size_t)row * D_MODEL + cw;
                size_t i1 = base + (size_t)(row + 8) * D_MODEL + cw;
                *(uint32_t*)(Ohi + i0) = pack_f16_hi(v0, v1);
                *(uint32_t*)(Ohi + i1) = pack_f16_hi(v2, v3);
                if (slot != 2) {   // V consumed single-fp16 in PV; hi only
                    *(uint32_t*)(Olo + i0) = pack_f16_lo(v0, v1);
                    *(uint32_t*)(Olo + i1) = pack_f16_lo(v2, v3);
                }
            }
    }
}

// ---------------------------------------------------------------------------
// Split fp32 -> (hi, lo) fp16, elementwise.
// ---------------------------------------------------------------------------
__global__ void k_split(const float4* __restrict__ in, uint2* __restrict__ hi,
                        uint2* __restrict__ lo, int n4)
{
    int i = blockIdx.x * blockDim.x + threadIdx.x;
    if (i >= n4) return;
    float4 v = in[i];
    float f[4] = {v.x, v.y, v.z, v.w};
    __half h[4], l[4];
#pragma unroll
    for (int j = 0; j < 4; j++) {
        h[j] = __float2half_rn(f[j]);
        l[j] = __float2half_rn(f[j] - __half2float(h[j]));
    }
    hi[i] = *(uint2*)h;
    lo[i] = *(uint2*)l;
}

// Transpose + split 4 weights in one launch (blockIdx.z selects slot).
__global__ void k_wsplit4(const float* __restrict__ W0, const float* __restrict__ W1,
                          const float* __restrict__ W2, const float* __restrict__ W3,
                          __half* __restrict__ Th, __half* __restrict__ Tl)
{
    __shared__ float t[32][33];
    const float* W = (blockIdx.z == 0) ? W0 : (blockIdx.z == 1) ? W1
                   : (blockIdx.z == 2) ? W2 : W3;
    const size_t wbase = (size_t)blockIdx.z * D_MODEL * D_MODEL;
    int k0 = blockIdx.x * 32, n0 = blockIdx.y * 32;
    int tx = threadIdx.x, ty = threadIdx.y;  // 32 x 8
#pragma unroll
    for (int i = 0; i < 4; i++)
        t[ty + 8 * i][tx] = W[(size_t)(k0 + ty + 8 * i) * D_MODEL + n0 + tx];
    __syncthreads();
#pragma unroll
    for (int i = 0; i < 4; i++) {
        float v = t[tx][ty + 8 * i];
        __half h = __float2half_rn(v);
        __half l = __float2half_rn(v - __half2float(h));
        size_t o = wbase + (size_t)(n0 + ty + 8 * i) * D_MODEL + k0 + tx;
        Th[o] = h;
        Tl[o] = l;
    }
}

// ---------------------------------------------------------------------------
// Flash attention: QK^T 3-term fp16, PV single-term (P and V single fp16).
// KV tile 128 keys, TWO-stage pipeline, 1 barrier per tile (8 tiles).
// ctx stored single fp16. (unchanged from round 13/14)
// ---------------------------------------------------------------------------
#define ATT_PAD 144
#define SMQ_H 0
#define SMQ_L 18432
#define SM_STAGE0 36864
#define ATT_KL (128 * ATT_PAD)                 // 18432
#define ATT_VH (2 * 128 * ATT_PAD)             // 36864
#define ATT_STG (3 * 128 * ATT_PAD)            // 55296: Kh,Kl,Vh (128 keys)
#define ATT_SMEM (SM_STAGE0 + 2 * ATT_STG)     // 147456
#define ATT_NT (SEQ / 128)                      // 8 tiles

__global__ __launch_bounds__(256, 1)
void attn_mma(const __half* __restrict__ QKVh, const __half* __restrict__ QKVl,
              __half* __restrict__ Chg)
{
    extern __shared__ char smc[];
    const uint32_t sb = smem_to_u32(smc);
    const int tid = threadIdx.x, lane = tid & 31, w = tid >> 5;
    const int b = blockIdx.y >> 4, h = blockIdx.y & 15;
    const int q0 = blockIdx.x * 128;
    const size_t rowB = (size_t)D_MODEL * 2;

    const char* Qh = (const char*)QKVh + ((size_t)(b * SEQ + q0) * D_MODEL + h * 64) * 2;
    const char* Ql = (const char*)QKVl + ((size_t)(b * SEQ + q0) * D_MODEL + h * 64) * 2;
    const char* Kh = (const char*)(QKVh + SLOT_SZ) + ((size_t)(b * SEQ) * D_MODEL + h * 64) * 2;
    const char* Kl = (const char*)(QKVl + SLOT_SZ) + ((size_t)(b * SEQ) * D_MODEL + h * 64) * 2;
    const char* Vh = (const char*)(QKVh + 2 * SLOT_SZ) + ((size_t)(b * SEQ) * D_MODEL + h * 64) * 2;

    // Q tile
    for (int i = tid; i < 1024; i += 256) {
        int r = i >> 3, c = i & 7;
        uint32_t so = (uint32_t)(r * ATT_PAD + c * 16);
        CP_ASYNC16(sb + SMQ_H + so, Qh + (size_t)r * rowB + c * 16);
        CP_ASYNC16(sb + SMQ_L + so, Ql + (size_t)r * rowB + c * 16);
    }
    CP_COMMIT();

    auto load_kv = [&](int tile, int st) {
        const uint32_t stB = sb + SM_STAGE0 + st * ATT_STG;
        const size_t n0b = (size_t)(tile * 128) * rowB;
        for (int i = tid; i < 1024; i += 256) {      // 128 rows x 8 x 16B
            int r = i >> 3, c = i & 7;
            size_t go = n0b + (size_t)r * rowB + c * 16;
            uint32_t so = (uint32_t)(r * ATT_PAD + c * 16);
            CP_ASYNC16(stB + so,          Kh + go);
            CP_ASYNC16(stB + ATT_KL + so, Kl + go);
            CP_ASYNC16(stB + ATT_VH + so, Vh + go);
        }
        CP_COMMIT();
    };

    load_kv(0, 0);
    CP_WAIT0();          // Q + tile0 complete
    __syncthreads();

    // Q A-fragments (loop-invariant)
    uint32_t qh[4][4], ql[4][4];
    {
        const uint32_t ao = (uint32_t)((w * 16 + (lane & 15)) * ATT_PAD + ((lane >> 4) & 1) * 16);
#pragma unroll
        for (int t = 0; t < 4; t++) {
            LDSM_X4(qh[t], sb + SMQ_H + ao + t * 32);
            LDSM_X4(ql[t], sb + SMQ_L + ao + t * 32);
        }
    }

    float o[8][4];
#pragma unroll
    for (int j = 0; j < 8; j++)
#pragma unroll
        for (int r = 0; r < 4; r++) o[j][r] = 0.f;
    float m0 = -CUDART_INF_F, m1 = -CUDART_INF_F, l0 = 0.f, l1 = 0.f;

    const uint32_t bo = (uint32_t)(((lane & 7) + ((lane >> 4) & 1) * 8) * ATT_PAD
                                   + ((lane >> 3) & 1) * 16);
    const uint32_t vo = (uint32_t)(((lane & 7) + ((lane >> 3) & 1) * 8) * ATT_PAD
                                   + ((lane >> 4) & 1) * 16);

#pragma unroll 1
    for (int tile = 0; tile < ATT_NT; tile++) {
        const int st = tile & 1;
        if (tile > 0) { CP_WAIT0(); __syncthreads(); }
        if (tile + 1 < ATT_NT) load_kv(tile + 1, st ^ 1);

        const uint32_t sbK = sb + SM_STAGE0 + st * ATT_STG;

        // S = Q K^T   (this warp: 16 q-rows x 128 keys)
        float s[16][4];
#pragma unroll
        for (int j = 0; j < 16; j++)
#pragma unroll
            for (int r = 0; r < 4; r++) s[j][r] = 0.f;

#pragma unroll
        for (int t = 0; t < 4; t++)
#pragma unroll
            for (int g2 = 0; g2 < 4; g2++) {
                const int g = g2 * 2;
                uint32_t kh4[2][4], kl4[2][4];
#pragma unroll
                for (int p = 0; p < 2; p++) {
                    uint32_t ro = bo + (uint32_t)((g + p) * 16 * ATT_PAD) + t * 32;
                    LDSM_X4(kh4[p], sbK + ro);
                    LDSM_X4(kl4[p], sbK + ATT_KL + ro);
                }
#pragma unroll
                for (int p = 0; p < 2; p++)
#pragma unroll
                    for (int hf = 0; hf < 2; hf++)
                        MMA16816(s[(g + p) * 2 + hf], qh[t], kh4[p][hf * 2], kh4[p][hf * 2 + 1]);
#pragma unroll
                for (int p = 0; p < 2; p++)
#pragma unroll
                    for (int hf = 0; hf < 2; hf++)
                        MMA16816(s[(g + p) * 2 + hf], ql[t], kh4[p][hf * 2], kh4[p][hf * 2 + 1]);
#pragma unroll
                for (int p = 0; p < 2; p++)
#pragma unroll
                    for (int hf = 0; hf < 2; hf++)
                        MMA16816(s[(g + p) * 2 + hf], qh[t], kl4[p][hf * 2], kl4[p][hf * 2 + 1]);
            }

        // Online softmax
        float mx0 = -CUDART_INF_F, mx1 = -CUDART_INF_F;
#pragma unroll
        for (int j = 0; j < 16; j++) {
            mx0 = fmaxf(mx0, fmaxf(s[j][0], s[j][1]));
            mx1 = fmaxf(mx1, fmaxf(s[j][2], s[j][3]));
        }
        mx0 = fmaxf(mx0, __shfl_xor_sync(0xffffffffu, mx0, 1));
        mx0 = fmaxf(mx0, __shfl_xor_sync(0xffffffffu, mx0, 2));
        mx1 = fmaxf(mx1, __shfl_xor_sync(0xffffffffu, mx1, 1));
        mx1 = fmaxf(mx1, __shfl_xor_sync(0xffffffffu, mx1, 2));
        float mn0 = fmaxf(m0, mx0), mn1 = fmaxf(m1, mx1);
        float a0 = __expf(m0 - mn0), a1 = __expf(m1 - mn1);
        m0 = mn0; m1 = mn1;
        float rs0 = 0.f, rs1 = 0.f;
#pragma unroll
        for (int j = 0; j < 16; j++) {
            s[j][0] = __expf(s[j][0] - mn0);
            s[j][1] = __expf(s[j][1] - mn0);
            s[j][2] = __expf(s[j][2] - mn1);
            s[j][3] = __expf(s[j][3] - mn1);
            rs0 += s[j][0] + s[j][1];
            rs1 += s[j][2] + s[j][3];
        }
        rs0 += __shfl_xor_sync(0xffffffffu, rs0, 1);
        rs0 += __shfl_xor_sync(0xffffffffu, rs0, 2);
        rs1 += __shfl_xor_sync(0xffffffffu, rs1, 1);
        rs1 += __shfl_xor_sync(0xffffffffu, rs1, 2);
        l0 = l0 * a0 + rs0;
        l1 = l1 * a1 + rs1;
#pragma unroll
        for (int j = 0; j < 8; j++) {
            o[j][0] *= a0; o[j][1] *= a0;
            o[j][2] *= a1; o[j][3] *= a1;
        }

        // O += P V : P single fp16, V single fp16.
#pragma unroll
        for (int t = 0; t < 8; t++) {
            uint32_t pah[4];
            pah[0] = pack_f16_hi(s[2 * t][0], s[2 * t][1]);
            pah[1] = pack_f16_hi(s[2 * t][2], s[2 * t][3]);
            pah[2] = pack_f16_hi(s[2 * t + 1][0], s[2 * t + 1][1]);
            pah[3] = pack_f16_hi(s[2 * t + 1][2], s[2 * t + 1][3]);
#pragma unroll
            for (int g = 0; g < 4; g++) {
                uint32_t ro = vo + (uint32_t)(t * 16 * ATT_PAD) + g * 32;
                uint32_t vh4[4];
                LDSM_X4_T(vh4, sbK + ATT_VH + ro);
#pragma unroll
                for (int hf = 0; hf < 2; hf++)
                    MMA16816(o[g * 2 + hf], pah, vh4[hf * 2], vh4[hf * 2 + 1]);
            }
        }
    }

    // Epilogue: normalize, store ctx single fp16.
    const float inv0 = 1.0f / l0, inv1 = 1.0f / l1;
    const int s0 = q0 + w * 16 + (lane >> 2);
    const int cl = (lane & 3) * 2;
#pragma unroll
    for (int j8 = 0; j8 < 8; j8++) {
        int col = h * 64 + j8 * 8 + cl;
        size_t i0 = (size_t)(b * SEQ + s0) * D_MODEL + col;
        size_t i1 = (size_t)(b * SEQ + s0 + 8) * D_MODEL + col;
        *(uint32_t*)(Chg + i0) = pack_f16_hi(o[j8][0] * inv0, o[j8][1] * inv0);
        *(uint32_t*)(Chg + i1) = pack_f16_hi(o[j8][2] * inv1, o[j8][3] * inv1);
    }
}

// ---------------------------------------------------------------------------
// Launch
// ---------------------------------------------------------------------------
extern "C" void kernel_launch(void* const* d_in, const int* in_sizes, int n_in,
                              void* d_out, int out_size)
{
    const float* x  = (const float*)d_in[0];
    const float* Wq = (const float*)d_in[1];
    const float* Wk = (const float*)d_in[2];
    const float* Wv = (const float*)d_in[3];
    const float* Wo = (const float*)d_in[4];
    float* out = (float*)d_out;

    __half *xhi, *xlo, *wthi, *wtlo, *qkvh, *qkvl, *ch;
    cudaGetSymbolAddress((void**)&xhi, g_xhi);
    cudaGetSymbolAddress((void**)&xlo, g_xlo);
    cudaGetSymbolAddress((void**)&wthi, g_wthi);
    cudaGetSymbolAddress((void**)&wtlo, g_wtlo);
    cudaGetSymbolAddress((void**)&qkvh, g_qkvh);
    cudaGetSymbolAddress((void**)&qkvl, g_qkvl);
    cudaGetSymbolAddress((void**)&ch, g_ch);

    cudaFuncSetAttribute(gemm_mma_f16<3>, cudaFuncAttributeMaxDynamicSharedMemorySize, GEMM_SMEM);
    cudaFuncSetAttribute(gemm_mma_f16<1>, cudaFuncAttributeMaxDynamicSharedMemorySize, GEMM_SMEM);
    cudaFuncSetAttribute(attn_mma, cudaFuncAttributeMaxDynamicSharedMemorySize, ATT_SMEM);

    const size_t WSLOT = (size_t)D_MODEL * D_MODEL;

    // All 4 weight transpose+splits in one launch.
    dim3 tgrid(32, 32, 4), tblk(32, 8);
    k_wsplit4<<<tgrid, tblk>>>(Wq, Wk, Wv, Wo, wthi, wtlo);

    const int n4 = M_TOK * D_MODEL / 4;
    k_split<<<n4 / 256, 256>>>((const float4*)x, (uint2*)xhi, (uint2*)xlo, n4);

    // QK projection (3-term, softmax-sensitive): N = 2048, weight slots 0-1.
    dim3 gqk(2 * D_MODEL / 128, M_TOK / 128);   // (16, 256)
    gemm_mma_f16<3><<<gqk, 256, GEMM_SMEM>>>(xhi, xlo, wthi, wtlo,
                                             nullptr, qkvh, qkvl, 0.125f, 1, 0,
                                             M_TOK, 2 * D_MODEL, D_MODEL);
    // V projection (1-term: xh * Wvh): N = 1024, weight slot 2.
    dim3 gv(D_MODEL / 128, M_TOK / 128);        // (8, 256)
    gemm_mma_f16<1><<<gv, 256, GEMM_SMEM>>>(xhi, xhi, wthi + 2 * WSLOT, wthi + 2 * WSLOT,
                                            nullptr, qkvh, qkvl, 1.0f, 1, 2,
                                            M_TOK, D_MODEL, D_MODEL);

    dim3 gAttn(SEQ / 128, BATCH * N_HEADS);     // (8, 512)
    attn_mma<<<gAttn, 256, ATT_SMEM>>>(qkvh, qkvl, ch);

    // Output projection (1-term: ctx_h * Woh).
    dim3 go(D_MODEL / 128, M_TOK / 128);        // (8, 256)
    gemm_mma_f16<1><<<go, 256, GEMM_SMEM>>>(ch, ch, wthi + 3 * WSLOT, wthi + 3 * WSLOT,
                                            out, nullptr, nullptr, 1.0f, 0, 0,
                                            M_TOK, D_MODEL, D_MODEL);
}

// round 16
// speedup vs baseline: 1.0573x; 1.0573x over previous
#include <cuda_runtime.h>
#include <cuda_fp16.h>
#include <math_constants.h>
#include <cstdint>

#define D_MODEL 1024
#define N_HEADS 16
#define HEAD_DIM 64
#define SEQ 1024
#define BATCH 32
#define M_TOK (BATCH * SEQ)   // 32768 tokens
#define SLOT_SZ ((size_t)M_TOK * D_MODEL)

// ---------------------------------------------------------------------------
// Scratch (alloc-free rule: __device__ globals).
// ---------------------------------------------------------------------------
__device__ __half g_xhi[SLOT_SZ];
__device__ __half g_xlo[SLOT_SZ];
__device__ __half g_wthi[(size_t)4 * D_MODEL * D_MODEL];
__device__ __half g_wtlo[(size_t)4 * D_MODEL * D_MODEL];
__device__ __half g_qkvh[3 * SLOT_SZ];
__device__ __half g_qkvl[3 * SLOT_SZ];
__device__ __half g_ch[SLOT_SZ];

// ---------------------------------------------------------------------------
// PTX helpers — plain compute_103-legal only (mma.sync / ldmatrix / cp.async).
// ---------------------------------------------------------------------------
__device__ __forceinline__ uint32_t smem_to_u32(const void* p) {
    uint32_t a;
    asm("{ .reg .u64 t; cvta.to.shared.u64 t, %1; cvt.u32.u64 %0, t; }" : "=r"(a) : "l"(p));
    return a;
}

#define CP_ASYNC16(sa, gp) \
    asm volatile("cp.async.cg.shared.global [%0], [%1], 16;" :: "r"(sa), "l"(gp))
#define CP_COMMIT() asm volatile("cp.async.commit_group;" ::: "memory")
#define CP_WAIT0()  asm volatile("cp.async.wait_group 0;" ::: "memory")

#define LDSM_X4(r, a) \
    asm volatile("ldmatrix.sync.aligned.m8n8.x4.shared.b16 {%0,%1,%2,%3}, [%4];" \
        : "=r"((r)[0]), "=r"((r)[1]), "=r"((r)[2]), "=r"((r)[3]) : "r"(a))

#define LDSM_X4_T(r, a) \
    asm volatile("ldmatrix.sync.aligned.m8n8.x4.trans.shared.b16 {%0,%1,%2,%3}, [%4];" \
        : "=r"((r)[0]), "=r"((r)[1]), "=r"((r)[2]), "=r"((r)[3]) : "r"(a))

#define MMA16816(c, a, b0v, b1v) \
    asm volatile("mma.sync.aligned.m16n8k16.row.col.f32.f16.f16.f32 " \
        "{%0,%1,%2,%3}, {%4,%5,%6,%7}, {%8,%9}, {%0,%1,%2,%3};" \
        : "+f"((c)[0]), "+f"((c)[1]), "+f"((c)[2]), "+f"((c)[3]) \
        : "r"((a)[0]), "r"((a)[1]), "r"((a)[2]), "r"((a)[3]), "r"(b0v), "r"(b1v))

__device__ __forceinline__ uint32_t pack_f16_hi(float a, float b) {
    __half2 t;
    t.x = __float2half_rn(a);
    t.y = __float2half_rn(b);
    return *(uint32_t*)&t;
}
__device__ __forceinline__ uint32_t pack_f16_lo(float a, float b) {
    __half ha = __float2half_rn(a), hb = __float2half_rn(b);
    __half2 t;
    t.x = __float2half_rn(a - __half2float(ha));
    t.y = __float2half_rn(b - __half2float(hb));
    return *(uint32_t*)&t;
}

// ---------------------------------------------------------------------------
// GEMM (R14 config — best measured): block 128x128, 4 warps (2x2),
// warp tile 64x64, 128 threads, TWO CTAs per SM (launch_bounds(128,2)).
// K-chunk 32, 2-stage cp.async pipeline.
// NT=3: Ah*Bh+Al*Bh+Ah*Bl.  NT=1: Ah*Bh.
// ---------------------------------------------------------------------------
#define PADB 80                           // 64B of K data + 16B pad
#define STG_AL 10240                      // 128*80
#define STG_BH 20480
#define STG_BL 30720
#define STAGE_BYTES 40960
#define GEMM_SMEM (2 * STAGE_BYTES)       // 81920 B/CTA -> 163840 for 2 CTAs

template <int NT>
__global__ __launch_bounds__(128, 2)
void gemm_mma_f16(const __half* __restrict__ Ahi, const __half* __restrict__ Alo,
                  const __half* __restrict__ Bhi, const __half* __restrict__ Blo,
                  float* __restrict__ Cf,
                  __half* __restrict__ Ohi, __half* __restrict__ Olo,
                  float scale, int bfmode, int slot_base, int M, int N, int K)
{
    extern __shared__ char smc[];
    const uint32_t sbase = smem_to_u32(smc);
    const int tid = threadIdx.x;
    const int lane = tid & 31, wid = tid >> 5;       // 0..3
    const int wm = wid >> 1, wn = wid & 1;           // warp grid 2(M) x 2(N)
    const int m0 = blockIdx.y * 128, n0 = blockIdx.x * 128;

    float acc[4][8][4];
#pragma unroll
    for (int i = 0; i < 4; i++)
#pragma unroll
        for (int j = 0; j < 8; j++)
#pragma unroll
            for (int r = 0; r < 4; r++) acc[i][j][r] = 0.f;

    const uint32_t aoff = (uint32_t)((wm * 64 + (lane & 15)) * PADB + ((lane >> 4) & 1) * 16);
    const uint32_t boff = (uint32_t)((wn * 64 + (lane & 7) + ((lane >> 4) & 1) * 8) * PADB
                                     + ((lane >> 3) & 1) * 16);

    auto load_stage = [&](int ch, int st) {
        const uint32_t sb = sbase + st * STAGE_BYTES;
        const size_t k0b = (size_t)ch * 64;           // 32 halves = 64 bytes
#pragma unroll
        for (int i = 0; i < 4; i++) {    // 128 rows x 4 x 16B per operand
            int s = tid + 128 * i;       // 0..511
            int row = s >> 2, c = s & 3;
            uint32_t so = (uint32_t)(row * PADB + c * 16);
            size_t ga = (size_t)(m0 + row) * K * 2 + k0b + c * 16;
            size_t gb = (size_t)(n0 + row) * K * 2 + k0b + c * 16;
            CP_ASYNC16(sb + so,          (const char*)Ahi + ga);
            CP_ASYNC16(sb + STG_BH + so, (const char*)Bhi + gb);
            if (NT >= 2) CP_ASYNC16(sb + STG_AL + so, (const char*)Alo + ga);
            if (NT == 3) CP_ASYNC16(sb + STG_BL + so, (const char*)Blo + gb);
        }
        CP_COMMIT();
    };

    const int NC = K / 32;               // 32 chunks
    load_stage(0, 0);

#pragma unroll 1
    for (int ch = 0; ch < NC; ch++) {
        const int st = ch & 1;
        CP_WAIT0();
        __syncthreads();                 // orders compute(ch-1) on stage st^1
        if (ch + 1 < NC) load_stage(ch + 1, st ^ 1);

        const uint32_t sb = sbase + st * STAGE_BYTES;
#pragma unroll
        for (int ks = 0; ks < 2; ks++) {
            const uint32_t kb = ks * 32;
            uint32_t ah[4][4], al[4][4];
#pragma unroll
            for (int i = 0; i < 4; i++) {
                LDSM_X4(ah[i], sb + aoff + i * (16 * PADB) + kb);
                if (NT >= 2) LDSM_X4(al[i], sb + STG_AL + aoff + i * (16 * PADB) + kb);
            }
#pragma unroll
            for (int j = 0; j < 4; j++) {
                uint32_t bh4[4], bl4[4];
                LDSM_X4(bh4, sb + STG_BH + boff + j * (16 * PADB) + kb);
                if (NT == 3) LDSM_X4(bl4, sb + STG_BL + boff + j * (16 * PADB) + kb);
#pragma unroll
                for (int i = 0; i < 4; i++)
#pragma unroll
                    for (int hf = 0; hf < 2; hf++)
                        MMA16816(acc[i][j * 2 + hf], ah[i], bh4[hf * 2], bh4[hf * 2 + 1]);
                if (NT >= 2) {
#pragma unroll
                    for (int i = 0; i < 4; i++)
#pragma unroll
                        for (int hf = 0; hf < 2; hf++)
                            MMA16816(acc[i][j * 2 + hf], al[i], bh4[hf * 2], bh4[hf * 2 + 1]);
                }
                if (NT == 3) {
#pragma unroll
                    for (int i = 0; i < 4; i++)
#pragma unroll
                        for (int hf = 0; hf < 2; hf++)
                            MMA16816(acc[i][j * 2 + hf], ah[i], bl4[hf * 2], bl4[hf * 2 + 1]);
                }
            }
        }
    }

    const int r = lane >> 2, cl = (lane & 3) * 2;
    if (!bfmode) {
#pragma unroll
        for (int i = 0; i < 4; i++)
#pragma unroll
            for (int j8 = 0; j8 < 8; j8++) {
                int row = m0 + wm * 64 + i * 16 + r;
                int col = n0 + wn * 64 + j8 * 8 + cl;
                *(float2*)(Cf + (size_t)row * N + col) =
                    make_float2(acc[i][j8][0], acc[i][j8][1]);
                *(float2*)(Cf + (size_t)(row + 8) * N + col) =
                    make_float2(acc[i][j8][2], acc[i][j8][3]);
            }
    } else {
#pragma unroll
        for (int i = 0; i < 4; i++)
#pragma unroll
            for (int j8 = 0; j8 < 8; j8++) {
                int row = m0 + wm * 64 + i * 16 + r;
                int col = n0 + wn * 64 + j8 * 8 + cl;
                int slot = slot_base + (col >> 10), cw = col & 1023;
                float sc = (slot == 0) ? scale : 1.0f;
                size_t base = (size_t)slot * SLOT_SZ;
                float v0 = acc[i][j8][0] * sc, v1 = acc[i][j8][1] * sc;
                float v2 = acc[i][j8][2] * sc, v3 = acc[i][j8][3] * sc;
                size_t i0 = base + (size_t)row * D_MODEL + cw;
                size_t i1 = base + (size_t)(row + 8) * D_MODEL + cw;
                *(uint32_t*)(Ohi + i0) = pack_f16_hi(v0, v1);
                *(uint32_t*)(Ohi + i1) = pack_f16_hi(v2, v3);
                if (slot != 2) {   // V consumed single-fp16 in PV; hi only
                    *(uint32_t*)(Olo + i0) = pack_f16_lo(v0, v1);
                    *(uint32_t*)(Olo + i1) = pack_f16_lo(v2, v3);
                }
            }
    }
}

// ---------------------------------------------------------------------------
// Split fp32 -> (hi, lo) fp16, elementwise.
// ---------------------------------------------------------------------------
__global__ void k_split(const float4* __restrict__ in, uint2* __restrict__ hi,
                        uint2* __restrict__ lo, int n4)
{
    int i = blockIdx.x * blockDim.x + threadIdx.x;
    if (i >= n4) return;
    float4 v = in[i];
    float f[4] = {v.x, v.y, v.z, v.w};
    __half h[4], l[4];
#pragma unroll
    for (int j = 0; j < 4; j++) {
        h[j] = __float2half_rn(f[j]);
        l[j] = __float2half_rn(f[j] - __half2float(h[j]));
    }
    hi[i] = *(uint2*)h;
    lo[i] = *(uint2*)l;
}

// Transpose + split 4 weights in one launch (blockIdx.z selects slot).
__global__ void k_wsplit4(const float* __restrict__ W0, const float* __restrict__ W1,
                          const float* __restrict__ W2, const float* __restrict__ W3,
                          __half* __restrict__ Th, __half* __restrict__ Tl)
{
    __shared__ float t[32][33];
    const float* W = (blockIdx.z == 0) ? W0 : (blockIdx.z == 1) ? W1
                   : (blockIdx.z == 2) ? W2 : W3;
    const size_t wbase = (size_t)blockIdx.z * D_MODEL * D_MODEL;
    int k0 = blockIdx.x * 32, n0 = blockIdx.y * 32;
    int tx = threadIdx.x, ty = threadIdx.y;  // 32 x 8
#pragma unroll
    for (int i = 0; i < 4; i++)
        t[ty + 8 * i][tx] = W[(size_t)(k0 + ty + 8 * i) * D_MODEL + n0 + tx];
    __syncthreads();
#pragma unroll
    for (int i = 0; i < 4; i++) {
        float v = t[tx][ty + 8 * i];
        __half h = __float2half_rn(v);
        __half l = __float2half_rn(v - __half2float(h));
        size_t o = wbase + (size_t)(n0 + ty + 8 * i) * D_MODEL + k0 + tx;
        Th[o] = h;
        Tl[o] = l;
    }
}

// ---------------------------------------------------------------------------
// Flash attention: QK^T 3-term fp16, PV single-term (P and V single fp16).
// KV tile 64 keys, 2-stage pipeline, TWO CTAs per SM (92KB smem,
// launch_bounds(256,2)) — co-resident CTA's MMAs overlap softmax phases.
// ctx stored single fp16.
// ---------------------------------------------------------------------------
#define ATT_PAD 144
#define SMQ_H 0
#define SMQ_L 18432
#define SM_STAGE0 36864
#define ATT_KL (64 * ATT_PAD)                  // 9216
#define ATT_VH (2 * 64 * ATT_PAD)              // 18432
#define ATT_STG (3 * 64 * ATT_PAD)             // 27648: Kh,Kl,Vh (64 keys)
#define ATT_SMEM (SM_STAGE0 + 2 * ATT_STG)     // 92160 -> 184320 for 2 CTAs
#define ATT_NT (SEQ / 64)                       // 16 tiles

__global__ __launch_bounds__(256, 2)
void attn_mma(const __half* __restrict__ QKVh, const __half* __restrict__ QKVl,
              __half* __restrict__ Chg)
{
    extern __shared__ char smc[];
    const uint32_t sb = smem_to_u32(smc);
    const int tid = threadIdx.x, lane = tid & 31, w = tid >> 5;
    const int b = blockIdx.y >> 4, h = blockIdx.y & 15;
    const int q0 = blockIdx.x * 128;
    const size_t rowB = (size_t)D_MODEL * 2;

    const char* Qh = (const char*)QKVh + ((size_t)(b * SEQ + q0) * D_MODEL + h * 64) * 2;
    const char* Ql = (const char*)QKVl + ((size_t)(b * SEQ + q0) * D_MODEL + h * 64) * 2;
    const char* Kh = (const char*)(QKVh + SLOT_SZ) + ((size_t)(b * SEQ) * D_MODEL + h * 64) * 2;
    const char* Kl = (const char*)(QKVl + SLOT_SZ) + ((size_t)(b * SEQ) * D_MODEL + h * 64) * 2;
    const char* Vh = (const char*)(QKVh + 2 * SLOT_SZ) + ((size_t)(b * SEQ) * D_MODEL + h * 64) * 2;

    // Q tile
    for (int i = tid; i < 1024; i += 256) {
        int r = i >> 3, c = i & 7;
        uint32_t so = (uint32_t)(r * ATT_PAD + c * 16);
        CP_ASYNC16(sb + SMQ_H + so, Qh + (size_t)r * rowB + c * 16);
        CP_ASYNC16(sb + SMQ_L + so, Ql + (size_t)r * rowB + c * 16);
    }
    CP_COMMIT();

    auto load_kv = [&](int tile, int st) {
        const uint32_t stB = sb + SM_STAGE0 + st * ATT_STG;
        const size_t n0b = (size_t)(tile * 64) * rowB;
        for (int i = tid; i < 512; i += 256) {       // 64 rows x 8 x 16B
            int r = i >> 3, c = i & 7;
            size_t go = n0b + (size_t)r * rowB + c * 16;
            uint32_t so = (uint32_t)(r * ATT_PAD + c * 16);
            CP_ASYNC16(stB + so,          Kh + go);
            CP_ASYNC16(stB + ATT_KL + so, Kl + go);
            CP_ASYNC16(stB + ATT_VH + so, Vh + go);
        }
        CP_COMMIT();
    };

    load_kv(0, 0);
    CP_WAIT0();          // Q + tile0 complete
    __syncthreads();

    // Q A-fragments (loop-invariant)
    uint32_t qh[4][4], ql[4][4];
    {
        const uint32_t ao = (uint32_t)((w * 16 + (lane & 15)) * ATT_PAD + ((lane >> 4) & 1) * 16);
#pragma unroll
        for (int t = 0; t < 4; t++) {
            LDSM_X4(qh[t], sb + SMQ_H + ao + t * 32);
            LDSM_X4(ql[t], sb + SMQ_L + ao + t * 32);
        }
    }

    float o[8][4];
#pragma unroll
    for (int j = 0; j < 8; j++)
#pragma unroll
        for (int r = 0; r < 4; r++) o[j][r] = 0.f;
    float m0 = -CUDART_INF_F, m1 = -CUDART_INF_F, l0 = 0.f, l1 = 0.f;

    const uint32_t bo = (uint32_t)(((lane & 7) + ((lane >> 4) & 1) * 8) * ATT_PAD
                                   + ((lane >> 3) & 1) * 16);
    const uint32_t vo = (uint32_t)(((lane & 7) + ((lane >> 3) & 1) * 8) * ATT_PAD
                                   + ((lane >> 4) & 1) * 16);

#pragma unroll 1
    for (int tile = 0; tile < ATT_NT; tile++) {
        const int st = tile & 1;
        if (tile > 0) { CP_WAIT0(); __syncthreads(); }
        if (tile + 1 < ATT_NT) load_kv(tile + 1, st ^ 1);

        const uint32_t sbK = sb + SM_STAGE0 + st * ATT_STG;

        // S = Q K^T   (this warp: 16 q-rows x 64 keys)
        float s[8][4];
#pragma unroll
        for (int j = 0; j < 8; j++)
#pragma unroll
            for (int r = 0; r < 4; r++) s[j][r] = 0.f;

#pragma unroll
        for (int t = 0; t < 4; t++)
#pragma unroll
            for (int g2 = 0; g2 < 2; g2++) {
                const int g = g2 * 2;
                uint32_t kh4[2][4], kl4[2][4];
#pragma unroll
                for (int p = 0; p < 2; p++) {
                    uint32_t ro = bo + (uint32_t)((g + p) * 16 * ATT_PAD) + t * 32;
                    LDSM_X4(kh4[p], sbK + ro);
                    LDSM_X4(kl4[p], sbK + ATT_KL + ro);
                }
#pragma unroll
                for (int p = 0; p < 2; p++)
#pragma unroll
                    for (int hf = 0; hf < 2; hf++)
                        MMA16816(s[(g + p) * 2 + hf], qh[t], kh4[p][hf * 2], kh4[p][hf * 2 + 1]);
#pragma unroll
                for (int p = 0; p < 2; p++)
#pragma unroll
                    for (int hf = 0; hf < 2; hf++)
                        MMA16816(s[(g + p) * 2 + hf], ql[t], kh4[p][hf * 2], kh4[p][hf * 2 + 1]);
#pragma unroll
                for (int p = 0; p < 2; p++)
#pragma unroll
                    for (int hf = 0; hf < 2; hf++)
                        MMA16816(s[(g + p) * 2 + hf], qh[t], kl4[p][hf * 2], kl4[p][hf * 2 + 1]);
            }

        // Online softmax (rows: lane>>2 and +8; 4 lanes per row group)
        float mx0 = -CUDART_INF_F, mx1 = -CUDART_INF_F;
#pragma unroll
        for (int j = 0; j < 8; j++) {
            mx0 = fmaxf(mx0, fmaxf(s[j][0], s[j][1]));
            mx1 = fmaxf(mx1, fmaxf(s[j][2], s[j][3]));
        }
        mx0 = fmaxf(mx0, __shfl_xor_sync(0xffffffffu, mx0, 1));
        mx0 = fmaxf(mx0, __shfl_xor_sync(0xffffffffu, mx0, 2));
        mx1 = fmaxf(mx1, __shfl_xor_sync(0xffffffffu, mx1, 1));
        mx1 = fmaxf(mx1, __shfl_xor_sync(0xffffffffu, mx1, 2));
        float mn0 = fmaxf(m0, mx0), mn1 = fmaxf(m1, mx1);
        float a0 = __expf(m0 - mn0), a1 = __expf(m1 - mn1);
        m0 = mn0; m1 = mn1;
        float rs0 = 0.f, rs1 = 0.f;
#pragma unroll
        for (int j = 0; j < 8; j++) {
            s[j][0] = __expf(s[j][0] - mn0);
            s[j][1] = __expf(s[j][1] - mn0);
            s[j][2] = __expf(s[j][2] - mn1);
            s[j][3] = __expf(s[j][3] - mn1);
            rs0 += s[j][0] + s[j][1];
            rs1 += s[j][2] + s[j][3];
        }
        rs0 += __shfl_xor_sync(0xffffffffu, rs0, 1);
        rs0 += __shfl_xor_sync(0xffffffffu, rs0, 2);
        rs1 += __shfl_xor_sync(0xffffffffu, rs1, 1);
        rs1 += __shfl_xor_sync(0xffffffffu, rs1, 2);
        l0 = l0 * a0 + rs0;
        l1 = l1 * a1 + rs1;
#pragma unroll
        for (int j = 0; j < 8; j++) {
            o[j][0] *= a0; o[j][1] *= a0;
            o[j][2] *= a1; o[j][3] *= a1;
        }

        // O += P V : P single fp16, V single fp16.
#pragma unroll
        for (int t = 0; t < 4; t++) {
            uint32_t pah[4];
            pah[0] = pack_f16_hi(s[2 * t][0], s[2 * t][1]);
            pah[1] = pack_f16_hi(s[2 * t][2], s[2 * t][3]);
            pah[2] = pack_f16_hi(s[2 * t + 1][0], s[2 * t + 1][1]);
            pah[3] = pack_f16_hi(s[2 * t + 1][2], s[2 * t + 1][3]);
#pragma unroll
            for (int g = 0; g < 4; g++) {
                uint32_t ro = vo + (uint32_t)(t * 16 * ATT_PAD) + g * 32;
                uint32_t vh4[4];
                LDSM_X4_T(vh4, sbK + ATT_VH + ro);
#pragma unroll
                for (int hf = 0; hf < 2; hf++)
                    MMA16816(o[g * 2 + hf], pah, vh4[hf * 2], vh4[hf * 2 + 1]);
            }
        }
    }

    // Epilogue: normalize, store ctx single fp16.
    const float inv0 = 1.0f / l0, inv1 = 1.0f / l1;
    const int s0 = q0 + w * 16 + (lane >> 2);
    const int cl = (lane & 3) * 2;
#pragma unroll
    for (int j8 = 0; j8 < 8; j8++) {
        int col = h * 64 + j8 * 8 + cl;
        size_t i0 = (size_t)(b * SEQ + s0) * D_MODEL + col;
        size_t i1 = (size_t)(b * SEQ + s0 + 8) * D_MODEL + col;
        *(uint32_t*)(Chg + i0) = pack_f16_hi(o[j8][0] * inv0, o[j8][1] * inv0);
        *(uint32_t*)(Chg + i1) = pack_f16_hi(o[j8][2] * inv1, o[j8][3] * inv1);
    }
}

// ---------------------------------------------------------------------------
// Launch
// ---------------------------------------------------------------------------
extern "C" void kernel_launch(void* const* d_in, const int* in_sizes, int n_in,
                              void* d_out, int out_size)
{
    const float* x  = (const float*)d_in[0];
    const float* Wq = (const float*)d_in[1];
    const float* Wk = (const float*)d_in[2];
    const float* Wv = (const float*)d_in[3];
    const float* Wo = (const float*)d_in[4];
    float* out = (float*)d_out;

    __half *xhi, *xlo, *wthi, *wtlo, *qkvh, *qkvl, *ch;
    cudaGetSymbolAddress((void**)&xhi, g_xhi);
    cudaGetSymbolAddress((void**)&xlo, g_xlo);
    cudaGetSymbolAddress((void**)&wthi, g_wthi);
    cudaGetSymbolAddress((void**)&wtlo, g_wtlo);
    cudaGetSymbolAddress((void**)&qkvh, g_qkvh);
    cudaGetSymbolAddress((void**)&qkvl, g_qkvl);
    cudaGetSymbolAddress((void**)&ch, g_ch);

    cudaFuncSetAttribute(gemm_mma_f16<3>, cudaFuncAttributeMaxDynamicSharedMemorySize, GEMM_SMEM);
    cudaFuncSetAttribute(gemm_mma_f16<1>, cudaFuncAttributeMaxDynamicSharedMemorySize, GEMM_SMEM);
    cudaFuncSetAttribute(attn_mma, cudaFuncAttributeMaxDynamicSharedMemorySize, ATT_SMEM);

    const size_t WSLOT = (size_t)D_MODEL * D_MODEL;

    // All 4 weight transpose+splits in one launch.
    dim3 tgrid(32, 32, 4), tblk(32, 8);
    k_wsplit4<<<tgrid, tblk>>>(Wq, Wk, Wv, Wo, wthi, wtlo);

    const int n4 = M_TOK * D_MODEL / 4;
    k_split<<<n4 / 256, 256>>>((const float4*)x, (uint2*)xhi, (uint2*)xlo, n4);

    // QK projection (3-term, softmax-sensitive): N = 2048, weight slots 0-1.
    dim3 gqk(2 * D_MODEL / 128, M_TOK / 128);   // (16, 256)
    gemm_mma_f16<3><<<gqk, 128, GEMM_SMEM>>>(xhi, xlo, wthi, wtlo,
                                             nullptr, qkvh, qkvl, 0.125f, 1, 0,
                                             M_TOK, 2 * D_MODEL, D_MODEL);
    // V projection (1-term: xh * Wvh): N = 1024, weight slot 2.
    dim3 gv(D_MODEL / 128, M_TOK / 128);        // (8, 256)
    gemm_mma_f16<1><<<gv, 128, GEMM_SMEM>>>(xhi, xhi, wthi + 2 * WSLOT, wthi + 2 * WSLOT,
                                            nullptr, qkvh, qkvl, 1.0f, 1, 2,
                                            M_TOK, D_MODEL, D_MODEL);

    dim3 gAttn(SEQ / 128, BATCH * N_HEADS);     // (8, 512)
    attn_mma<<<gAttn, 256, ATT_SMEM>>>(qkvh, qkvl, ch);

    // Output projection (1-term: ctx_h * Woh).
    dim3 go(D_MODEL / 128, M_TOK / 128);        // (8, 256)
    gemm_mma_f16<1><<<go, 128, GEMM_SMEM>>>(ch, ch, wthi + 3 * WSLOT, wthi + 3 * WSLOT,
                                            out, nullptr, nullptr, 1.0f, 0, 0,
                                            M_TOK, D_MODEL, D_MODEL);
}

// round 17
// speedup vs baseline: 1.1249x; 1.0640x over previous
#include <cuda_runtime.h>
#include <cuda_fp16.h>
#include <math_constants.h>
#include <cstdint>

#define D_MODEL 1024
#define N_HEADS 16
#define HEAD_DIM 64
#define SEQ 1024
#define BATCH 32
#define M_TOK (BATCH * SEQ)   // 32768 tokens
#define SLOT_SZ ((size_t)M_TOK * D_MODEL)

// ---------------------------------------------------------------------------
// Scratch (alloc-free rule: __device__ globals).
// ---------------------------------------------------------------------------
__device__ __half g_xhi[SLOT_SZ];
__device__ __half g_xlo[SLOT_SZ];
__device__ __half g_wthi[(size_t)4 * D_MODEL * D_MODEL];
__device__ __half g_wtlo[(size_t)4 * D_MODEL * D_MODEL];
__device__ __half g_qkvh[3 * SLOT_SZ];
__device__ __half g_qkvl[3 * SLOT_SZ];
__device__ __half g_ch[SLOT_SZ];

// ---------------------------------------------------------------------------
// PTX helpers — plain compute_103-legal only (mma.sync / ldmatrix / cp.async).
// ---------------------------------------------------------------------------
__device__ __forceinline__ uint32_t smem_to_u32(const void* p) {
    uint32_t a;
    asm("{ .reg .u64 t; cvta.to.shared.u64 t, %1; cvt.u32.u64 %0, t; }" : "=r"(a) : "l"(p));
    return a;
}

#define CP_ASYNC16(sa, gp) \
    asm volatile("cp.async.cg.shared.global [%0], [%1], 16;" :: "r"(sa), "l"(gp))
#define CP_COMMIT() asm volatile("cp.async.commit_group;" ::: "memory")
#define CP_WAIT0()  asm volatile("cp.async.wait_group 0;" ::: "memory")
#define CP_WAIT2()  asm volatile("cp.async.wait_group 2;" ::: "memory")

#define LDSM_X4(r, a) \
    asm volatile("ldmatrix.sync.aligned.m8n8.x4.shared.b16 {%0,%1,%2,%3}, [%4];" \
        : "=r"((r)[0]), "=r"((r)[1]), "=r"((r)[2]), "=r"((r)[3]) : "r"(a))

#define LDSM_X4_T(r, a) \
    asm volatile("ldmatrix.sync.aligned.m8n8.x4.trans.shared.b16 {%0,%1,%2,%3}, [%4];" \
        : "=r"((r)[0]), "=r"((r)[1]), "=r"((r)[2]), "=r"((r)[3]) : "r"(a))

#define MMA16816(c, a, b0v, b1v) \
    asm volatile("mma.sync.aligned.m16n8k16.row.col.f32.f16.f16.f32 " \
        "{%0,%1,%2,%3}, {%4,%5,%6,%7}, {%8,%9}, {%0,%1,%2,%3};" \
        : "+f"((c)[0]), "+f"((c)[1]), "+f"((c)[2]), "+f"((c)[3]) \
        : "r"((a)[0]), "r"((a)[1]), "r"((a)[2]), "r"((a)[3]), "r"(b0v), "r"(b1v))

__device__ __forceinline__ uint32_t pack_f16_hi(float a, float b) {
    __half2 t;
    t.x = __float2half_rn(a);
    t.y = __float2half_rn(b);
    return *(uint32_t*)&t;
}
__device__ __forceinline__ uint32_t pack_f16_lo(float a, float b) {
    __half ha = __float2half_rn(a), hb = __float2half_rn(b);
    __half2 t;
    t.x = __float2half_rn(a - __half2float(ha));
    t.y = __float2half_rn(b - __half2float(hb));
    return *(uint32_t*)&t;
}

// ---------------------------------------------------------------------------
// GEMM: block 128x128, 4 warps (2x2), warp tile 64x64, 128 threads,
// TWO CTAs per SM (launch_bounds(128,2)). K-chunk 32.
// NT=3: 2-stage (40.9KB/stage), CP_WAIT0 — compute covers latency.
// NT=1: 4-stage (20.5KB/stage), CP_WAIT2 — 2-3 chunk load lead hides DRAM.
// Total smem identical (81.9KB/CTA). Per-acc MMA order unchanged.
// ---------------------------------------------------------------------------
#define PADB 80                           // 64B of K data + 16B pad
#define OPER 10240                        // 128*80 per operand
#define GEMM_SMEM 81920                   // per CTA; x2 CTAs = 163840

template <int NT>
__global__ __launch_bounds__(128, 2)
void gemm_mma_f16(const __half* __restrict__ Ahi, const __half* __restrict__ Alo,
                  const __half* __restrict__ Bhi, const __half* __restrict__ Blo,
                  float* __restrict__ Cf,
                  __half* __restrict__ Ohi, __half* __restrict__ Olo,
                  float scale, int bfmode, int slot_base, int M, int N, int K)
{
    constexpr int NSTG = (NT == 1) ? 4 : 2;
    constexpr uint32_t STGB = (NT == 1) ? (2 * OPER) : (4 * OPER);
    // In-stage offsets: A@0; [Al@OPER if NT>=2]; Bh; [Bl if NT==3]
    constexpr uint32_t OFF_AL = OPER;
    constexpr uint32_t OFF_BH = (NT == 1) ? OPER : (2 * OPER);
    constexpr uint32_t OFF_BL = 3 * OPER;

    extern __shared__ char smc[];
    const uint32_t sbase = smem_to_u32(smc);
    const int tid = threadIdx.x;
    const int lane = tid & 31, wid = tid >> 5;       // 0..3
    const int wm = wid >> 1, wn = wid & 1;           // warp grid 2(M) x 2(N)
    const int m0 = blockIdx.y * 128, n0 = blockIdx.x * 128;

    float acc[4][8][4];
#pragma unroll
    for (int i = 0; i < 4; i++)
#pragma unroll
        for (int j = 0; j < 8; j++)
#pragma unroll
            for (int r = 0; r < 4; r++) acc[i][j][r] = 0.f;

    const uint32_t aoff = (uint32_t)((wm * 64 + (lane & 15)) * PADB + ((lane >> 4) & 1) * 16);
    const uint32_t boff = (uint32_t)((wn * 64 + (lane & 7) + ((lane >> 4) & 1) * 8) * PADB
                                     + ((lane >> 3) & 1) * 16);

    auto load_stage = [&](int ch, int st) {
        const uint32_t sb = sbase + st * STGB;
        const size_t k0b = (size_t)ch * 64;           // 32 halves = 64 bytes
#pragma unroll
        for (int i = 0; i < 4; i++) {    // 128 rows x 4 x 16B per operand
            int s = tid + 128 * i;       // 0..511
            int row = s >> 2, c = s & 3;
            uint32_t so = (uint32_t)(row * PADB + c * 16);
            size_t ga = (size_t)(m0 + row) * K * 2 + k0b + c * 16;
            size_t gb = (size_t)(n0 + row) * K * 2 + k0b + c * 16;
            CP_ASYNC16(sb + so,          (const char*)Ahi + ga);
            CP_ASYNC16(sb + OFF_BH + so, (const char*)Bhi + gb);
            if (NT >= 2) CP_ASYNC16(sb + OFF_AL + so, (const char*)Alo + ga);
            if (NT == 3) CP_ASYNC16(sb + OFF_BL + so, (const char*)Blo + gb);
        }
        CP_COMMIT();
    };

    const int NC = K / 32;               // 32 chunks
    load_stage(0, 0);
    if (NSTG == 4) { load_stage(1, 1); load_stage(2, 2); }

#pragma unroll 1
    for (int ch = 0; ch < NC; ch++) {
        const int st = ch % NSTG;
        if (NSTG == 4) { CP_WAIT2(); } else { CP_WAIT0(); }
        __syncthreads();                 // orders compute of the reused stage
        const int pre = ch + NSTG - 1;
        if (pre < NC) load_stage(pre, pre % NSTG);

        const uint32_t sb = sbase + st * STGB;
#pragma unroll
        for (int ks = 0; ks < 2; ks++) {
            const uint32_t kb = ks * 32;
            uint32_t ah[4][4], al[4][4];
#pragma unroll
            for (int i = 0; i < 4; i++) {
                LDSM_X4(ah[i], sb + aoff + i * (16 * PADB) + kb);
                if (NT >= 2) LDSM_X4(al[i], sb + OFF_AL + aoff + i * (16 * PADB) + kb);
            }
#pragma unroll
            for (int j = 0; j < 4; j++) {
                uint32_t bh4[4], bl4[4];
                LDSM_X4(bh4, sb + OFF_BH + boff + j * (16 * PADB) + kb);
                if (NT == 3) LDSM_X4(bl4, sb + OFF_BL + boff + j * (16 * PADB) + kb);
#pragma unroll
                for (int i = 0; i < 4; i++)
#pragma unroll
                    for (int hf = 0; hf < 2; hf++)
                        MMA16816(acc[i][j * 2 + hf], ah[i], bh4[hf * 2], bh4[hf * 2 + 1]);
                if (NT >= 2) {
#pragma unroll
                    for (int i = 0; i < 4; i++)
#pragma unroll
                        for (int hf = 0; hf < 2; hf++)
                            MMA16816(acc[i][j * 2 + hf], al[i], bh4[hf * 2], bh4[hf * 2 + 1]);
                }
                if (NT == 3) {
#pragma unroll
                    for (int i = 0; i < 4; i++)
#pragma unroll
                        for (int hf = 0; hf < 2; hf++)
                            MMA16816(acc[i][j * 2 + hf], ah[i], bl4[hf * 2], bl4[hf * 2 + 1]);
                }
            }
        }
    }

    const int r = lane >> 2, cl = (lane & 3) * 2;
    if (!bfmode) {
#pragma unroll
        for (int i = 0; i < 4; i++)
#pragma unroll
            for (int j8 = 0; j8 < 8; j8++) {
                int row = m0 + wm * 64 + i * 16 + r;
                int col = n0 + wn * 64 + j8 * 8 + cl;
                *(float2*)(Cf + (size_t)row * N + col) =
                    make_float2(acc[i][j8][0], acc[i][j8][1]);
                *(float2*)(Cf + (size_t)(row + 8) * N + col) =
                    make_float2(acc[i][j8][2], acc[i][j8][3]);
            }
    } else {
#pragma unroll
        for (int i = 0; i < 4; i++)
#pragma unroll
            for (int j8 = 0; j8 < 8; j8++) {
                int row = m0 + wm * 64 + i * 16 + r;
                int col = n0 + wn * 64 + j8 * 8 + cl;
                int slot = slot_base + (col >> 10), cw = col & 1023;
                float sc = (slot == 0) ? scale : 1.0f;
                size_t base = (size_t)slot * SLOT_SZ;
                float v0 = acc[i][j8][0] * sc, v1 = acc[i][j8][1] * sc;
                float v2 = acc[i][j8][2] * sc, v3 = acc[i][j8][3] * sc;
                size_t i0 = base + (size_t)row * D_MODEL + cw;
                size_t i1 = base + (size_t)(row + 8) * D_MODEL + cw;
                *(uint32_t*)(Ohi + i0) = pack_f16_hi(v0, v1);
                *(uint32_t*)(Ohi + i1) = pack_f16_hi(v2, v3);
                if (slot != 2) {   // V consumed single-fp16 in PV; hi only
                    *(uint32_t*)(Olo + i0) = pack_f16_lo(v0, v1);
                    *(uint32_t*)(Olo + i1) = pack_f16_lo(v2, v3);
                }
            }
    }
}

// ---------------------------------------------------------------------------
// Split fp32 -> (hi, lo) fp16, elementwise.
// ---------------------------------------------------------------------------
__global__ void k_split(const float4* __restrict__ in, uint2* __restrict__ hi,
                        uint2* __restrict__ lo, int n4)
{
    int i = blockIdx.x * blockDim.x + threadIdx.x;
    if (i >= n4) return;
    float4 v = in[i];
    float f[4] = {v.x, v.y, v.z, v.w};
    __half h[4], l[4];
#pragma unroll
    for (int j = 0; j < 4; j++) {
        h[j] = __float2half_rn(f[j]);
        l[j] = __float2half_rn(f[j] - __half2float(h[j]));
    }
    hi[i] = *(uint2*)h;
    lo[i] = *(uint2*)l;
}

// Transpose + split 4 weights in one launch (blockIdx.z selects slot).
__global__ void k_wsplit4(const float* __restrict__ W0, const float* __restrict__ W1,
                          const float* __restrict__ W2, const float* __restrict__ W3,
                          __half* __restrict__ Th, __half* __restrict__ Tl)
{
    __shared__ float t[32][33];
    const float* W = (blockIdx.z == 0) ? W0 : (blockIdx.z == 1) ? W1
                   : (blockIdx.z == 2) ? W2 : W3;
    const size_t wbase = (size_t)blockIdx.z * D_MODEL * D_MODEL;
    int k0 = blockIdx.x * 32, n0 = blockIdx.y * 32;
    int tx = threadIdx.x, ty = threadIdx.y;  // 32 x 8
#pragma unroll
    for (int i = 0; i < 4; i++)
        t[ty + 8 * i][tx] = W[(size_t)(k0 + ty + 8 * i) * D_MODEL + n0 + tx];
    __syncthreads();
#pragma unroll
    for (int i = 0; i < 4; i++) {
        float v = t[tx][ty + 8 * i];
        __half h = __float2half_rn(v);
        __half l = __float2half_rn(v - __half2float(h));
        size_t o = wbase + (size_t)(n0 + ty + 8 * i) * D_MODEL + k0 + tx;
        Th[o] = h;
        Tl[o] = l;
    }
}

// ---------------------------------------------------------------------------
// Flash attention: QK^T 3-term fp16, PV single-term (P and V single fp16).
// KV tile 64 keys, 2-stage pipeline, TWO CTAs per SM. (unchanged from R16)
// ---------------------------------------------------------------------------
#define ATT_PAD 144
#define SMQ_H 0
#define SMQ_L 18432
#define SM_STAGE0 36864
#define ATT_KL (64 * ATT_PAD)                  // 9216
#define ATT_VH (2 * 64 * ATT_PAD)              // 18432
#define ATT_STG (3 * 64 * ATT_PAD)             // 27648: Kh,Kl,Vh (64 keys)
#define ATT_SMEM (SM_STAGE0 + 2 * ATT_STG)     // 92160 -> 184320 for 2 CTAs
#define ATT_NT (SEQ / 64)                       // 16 tiles

__global__ __launch_bounds__(256, 2)
void attn_mma(const __half* __restrict__ QKVh, const __half* __restrict__ QKVl,
              __half* __restrict__ Chg)
{
    extern __shared__ char smc[];
    const uint32_t sb = smem_to_u32(smc);
    const int tid = threadIdx.x, lane = tid & 31, w = tid >> 5;
    const int b = blockIdx.y >> 4, h = blockIdx.y & 15;
    const int q0 = blockIdx.x * 128;
    const size_t rowB = (size_t)D_MODEL * 2;

    const char* Qh = (const char*)QKVh + ((size_t)(b * SEQ + q0) * D_MODEL + h * 64) * 2;
    const char* Ql = (const char*)QKVl + ((size_t)(b * SEQ + q0) * D_MODEL + h * 64) * 2;
    const char* Kh = (const char*)(QKVh + SLOT_SZ) + ((size_t)(b * SEQ) * D_MODEL + h * 64) * 2;
    const char* Kl = (const char*)(QKVl + SLOT_SZ) + ((size_t)(b * SEQ) * D_MODEL + h * 64) * 2;
    const char* Vh = (const char*)(QKVh + 2 * SLOT_SZ) + ((size_t)(b * SEQ) * D_MODEL + h * 64) * 2;

    // Q tile
    for (int i = tid; i < 1024; i += 256) {
        int r = i >> 3, c = i & 7;
        uint32_t so = (uint32_t)(r * ATT_PAD + c * 16);
        CP_ASYNC16(sb + SMQ_H + so, Qh + (size_t)r * rowB + c * 16);
        CP_ASYNC16(sb + SMQ_L + so, Ql + (size_t)r * rowB + c * 16);
    }
    CP_COMMIT();

    auto load_kv = [&](int tile, int st) {
        const uint32_t stB = sb + SM_STAGE0 + st * ATT_STG;
        const size_t n0b = (size_t)(tile * 64) * rowB;
        for (int i = tid; i < 512; i += 256) {       // 64 rows x 8 x 16B
            int r = i >> 3, c = i & 7;
            size_t go = n0b + (size_t)r * rowB + c * 16;
            uint32_t so = (uint32_t)(r * ATT_PAD + c * 16);
            CP_ASYNC16(stB + so,          Kh + go);
            CP_ASYNC16(stB + ATT_KL + so, Kl + go);
            CP_ASYNC16(stB + ATT_VH + so, Vh + go);
        }
        CP_COMMIT();
    };

    load_kv(0, 0);
    CP_WAIT0();          // Q + tile0 complete
    __syncthreads();

    // Q A-fragments (loop-invariant)
    uint32_t qh[4][4], ql[4][4];
    {
        const uint32_t ao = (uint32_t)((w * 16 + (lane & 15)) * ATT_PAD + ((lane >> 4) & 1) * 16);
#pragma unroll
        for (int t = 0; t < 4; t++) {
            LDSM_X4(qh[t], sb + SMQ_H + ao + t * 32);
            LDSM_X4(ql[t], sb + SMQ_L + ao + t * 32);
        }
    }

    float o[8][4];
#pragma unroll
    for (int j = 0; j < 8; j++)
#pragma unroll
        for (int r = 0; r < 4; r++) o[j][r] = 0.f;
    float m0 = -CUDART_INF_F, m1 = -CUDART_INF_F, l0 = 0.f, l1 = 0.f;

    const uint32_t bo = (uint32_t)(((lane & 7) + ((lane >> 4) & 1) * 8) * ATT_PAD
                                   + ((lane >> 3) & 1) * 16);
    const uint32_t vo = (uint32_t)(((lane & 7) + ((lane >> 3) & 1) * 8) * ATT_PAD
                                   + ((lane >> 4) & 1) * 16);

#pragma unroll 1
    for (int tile = 0; tile < ATT_NT; tile++) {
        const int st = tile & 1;
        if (tile > 0) { CP_WAIT0(); __syncthreads(); }
        if (tile + 1 < ATT_NT) load_kv(tile + 1, st ^ 1);

        const uint32_t sbK = sb + SM_STAGE0 + st * ATT_STG;

        // S = Q K^T   (this warp: 16 q-rows x 64 keys)
        float s[8][4];
#pragma unroll
        for (int j = 0; j < 8; j++)
#pragma unroll
            for (int r = 0; r < 4; r++) s[j][r] = 0.f;

#pragma unroll
        for (int t = 0; t < 4; t++)
#pragma unroll
            for (int g2 = 0; g2 < 2; g2++) {
                const int g = g2 * 2;
                uint32_t kh4[2][4], kl4[2][4];
#pragma unroll
                for (int p = 0; p < 2; p++) {
                    uint32_t ro = bo + (uint32_t)((g + p) * 16 * ATT_PAD) + t * 32;
                    LDSM_X4(kh4[p], sbK + ro);
                    LDSM_X4(kl4[p], sbK + ATT_KL + ro);
                }
#pragma unroll
                for (int p = 0; p < 2; p++)
#pragma unroll
                    for (int hf = 0; hf < 2; hf++)
                        MMA16816(s[(g + p) * 2 + hf], qh[t], kh4[p][hf * 2], kh4[p][hf * 2 + 1]);
#pragma unroll
                for (int p = 0; p < 2; p++)
#pragma unroll
                    for (int hf = 0; hf < 2; hf++)
                        MMA16816(s[(g + p) * 2 + hf], ql[t], kh4[p][hf * 2], kh4[p][hf * 2 + 1]);
#pragma unroll
                for (int p = 0; p < 2; p++)
#pragma unroll
                    for (int hf = 0; hf < 2; hf++)
                        MMA16816(s[(g + p) * 2 + hf], qh[t], kl4[p][hf * 2], kl4[p][hf * 2 + 1]);
            }

        // Online softmax (rows: lane>>2 and +8; 4 lanes per row group)
        float mx0 = -CUDART_INF_F, mx1 = -CUDART_INF_F;
#pragma unroll
        for (int j = 0; j < 8; j++) {
            mx0 = fmaxf(mx0, fmaxf(s[j][0], s[j][1]));
            mx1 = fmaxf(mx1, fmaxf(s[j][2], s[j][3]));
        }
        mx0 = fmaxf(mx0, __shfl_xor_sync(0xffffffffu, mx0, 1));
        mx0 = fmaxf(mx0, __shfl_xor_sync(0xffffffffu, mx0, 2));
        mx1 = fmaxf(mx1, __shfl_xor_sync(0xffffffffu, mx1, 1));
        mx1 = fmaxf(mx1, __shfl_xor_sync(0xffffffffu, mx1, 2));
        float mn0 = fmaxf(m0, mx0), mn1 = fmaxf(m1, mx1);
        float a0 = __expf(m0 - mn0), a1 = __expf(m1 - mn1);
        m0 = mn0; m1 = mn1;
        float rs0 = 0.f, rs1 = 0.f;
#pragma unroll
        for (int j = 0; j < 8; j++) {
            s[j][0] = __expf(s[j][0] - mn0);
            s[j][1] = __expf(s[j][1] - mn0);
            s[j][2] = __expf(s[j][2] - mn1);
            s[j][3] = __expf(s[j][3] - mn1);
            rs0 += s[j][0] + s[j][1];
            rs1 += s[j][2] + s[j][3];
        }
        rs0 += __shfl_xor_sync(0xffffffffu, rs0, 1);
        rs0 += __shfl_xor_sync(0xffffffffu, rs0, 2);
        rs1 += __shfl_xor_sync(0xffffffffu, rs1, 1);
        rs1 += __shfl_xor_sync(0xffffffffu, rs1, 2);
        l0 = l0 * a0 + rs0;
        l1 = l1 * a1 + rs1;
#pragma unroll
        for (int j = 0; j < 8; j++) {
            o[j][0] *= a0; o[j][1] *= a0;
            o[j][2] *= a1; o[j][3] *= a1;
        }

        // O += P V : P single fp16, V single fp16.
#pragma unroll
        for (int t = 0; t < 4; t++) {
            uint32_t pah[4];
            pah[0] = pack_f16_hi(s[2 * t][0], s[2 * t][1]);
            pah[1] = pack_f16_hi(s[2 * t][2], s[2 * t][3]);
            pah[2] = pack_f16_hi(s[2 * t + 1][0], s[2 * t + 1][1]);
            pah[3] = pack_f16_hi(s[2 * t + 1][2], s[2 * t + 1][3]);
#pragma unroll
            for (int g = 0; g < 4; g++) {
                uint32_t ro = vo + (uint32_t)(t * 16 * ATT_PAD) + g * 32;
                uint32_t vh4[4];
                LDSM_X4_T(vh4, sbK + ATT_VH + ro);
#pragma unroll
                for (int hf = 0; hf < 2; hf++)
                    MMA16816(o[g * 2 + hf], pah, vh4[hf * 2], vh4[hf * 2 + 1]);
            }
        }
    }

    // Epilogue: normalize, store ctx single fp16.
    const float inv0 = 1.0f / l0, inv1 = 1.0f / l1;
    const int s0 = q0 + w * 16 + (lane >> 2);
    const int cl = (lane & 3) * 2;
#pragma unroll
    for (int j8 = 0; j8 < 8; j8++) {
        int col = h * 64 + j8 * 8 + cl;
        size_t i0 = (size_t)(b * SEQ + s0) * D_MODEL + col;
        size_t i1 = (size_t)(b * SEQ + s0 + 8) * D_MODEL + col;
        *(uint32_t*)(Chg + i0) = pack_f16_hi(o[j8][0] * inv0, o[j8][1] * inv0);
        *(uint32_t*)(Chg + i1) = pack_f16_hi(o[j8][2] * inv1, o[j8][3] * inv1);
    }
}

// ---------------------------------------------------------------------------
// Launch
// ---------------------------------------------------------------------------
extern "C" void kernel_launch(void* const* d_in, const int* in_sizes, int n_in,
                              void* d_out, int out_size)
{
    const float* x  = (const float*)d_in[0];
    const float* Wq = (const float*)d_in[1];
    const float* Wk = (const float*)d_in[2];
    const float* Wv = (const float*)d_in[3];
    const float* Wo = (const float*)d_in[4];
    float* out = (float*)d_out;

    __half *xhi, *xlo, *wthi, *wtlo, *qkvh, *qkvl, *ch;
    cudaGetSymbolAddress((void**)&xhi, g_xhi);
    cudaGetSymbolAddress((void**)&xlo, g_xlo);
    cudaGetSymbolAddress((void**)&wthi, g_wthi);
    cudaGetSymbolAddress((void**)&wtlo, g_wtlo);
    cudaGetSymbolAddress((void**)&qkvh, g_qkvh);
    cudaGetSymbolAddress((void**)&qkvl, g_qkvl);
    cudaGetSymbolAddress((void**)&ch, g_ch);

    cudaFuncSetAttribute(gemm_mma_f16<3>, cudaFuncAttributeMaxDynamicSharedMemorySize, GEMM_SMEM);
    cudaFuncSetAttribute(gemm_mma_f16<1>, cudaFuncAttributeMaxDynamicSharedMemorySize, GEMM_SMEM);
    cudaFuncSetAttribute(attn_mma, cudaFuncAttributeMaxDynamicSharedMemorySize, ATT_SMEM);

    const size_t WSLOT = (size_t)D_MODEL * D_MODEL;

    // All 4 weight transpose+splits in one launch.
    dim3 tgrid(32, 32, 4), tblk(32, 8);
    k_wsplit4<<<tgrid, tblk>>>(Wq, Wk, Wv, Wo, wthi, wtlo);

    const int n4 = M_TOK * D_MODEL / 4;
    k_split<<<n4 / 256, 256>>>((const float4*)x, (uint2*)xhi, (uint2*)xlo, n4);

    // QK projection (3-term, softmax-sensitive): N = 2048, weight slots 0-1.
    dim3 gqk(2 * D_MODEL / 128, M_TOK / 128);   // (16, 256)
    gemm_mma_f16<3><<<gqk, 128, GEMM_SMEM>>>(xhi, xlo, wthi, wtlo,
                                             nullptr, qkvh, qkvl, 0.125f, 1, 0,
                                             M_TOK, 2 * D_MODEL, D_MODEL);
    // V projection (1-term: xh * Wvh): N = 1024, weight slot 2.
    dim3 gv(D_MODEL / 128, M_TOK / 128);        // (8, 256)
    gemm_mma_f16<1><<<gv, 128, GEMM_SMEM>>>(xhi, xhi, wthi + 2 * WSLOT, wthi + 2 * WSLOT,
                                            nullptr, qkvh, qkvl, 1.0f, 1, 2,
                                            M_TOK, D_MODEL, D_MODEL);

    dim3 gAttn(SEQ / 128, BATCH * N_HEADS);     // (8, 512)
    attn_mma<<<gAttn, 256, ATT_SMEM>>>(qkvh, qkvl, ch);

    // Output projection (1-term: ctx_h * Woh).
    dim3 go(D_MODEL / 128, M_TOK / 128);        // (8, 256)
    gemm_mma_f16<1><<<go, 128, GEMM_SMEM>>>(ch, ch, wthi + 3 * WSLOT, wthi + 3 * WSLOT,
                                            out, nullptr, nullptr, 1.0f, 0, 0,
                                            M_TOK, D_MODEL, D_MODEL);
}